// round 3
// baseline (speedup 1.0000x reference)
#include <cuda_runtime.h>

#define N_NODES 48
#define N_EDGES 192
#define DIM     1024
#define NN      (N_NODES * N_NODES)   // 2304
#define EE      (N_EDGES * N_EDGES)   // 36864
#define OUT_DIM NN                    // 2304
#define SPLITK  16
#define KC      (DIM / SPLITK)        // 64

// Scratch (no cudaMalloc allowed)
__device__ float g_cn[DIM];
__device__ float g_ce[DIM];
__device__ float g_Mp[NN];
__device__ float g_MePart[SPLITK][EE];

__device__ __forceinline__ float softplus_act(float x) {
    // relu(softplus(x) - 0.5)
    float sp = (x > 20.f) ? x : log1pf(expf(x));
    float v = sp - 0.5f;
    return v > 0.f ? v : 0.f;
}

// ---------------------------------------------------------------- zero output
__global__ void k_zero(float4* __restrict__ out, int n4) {
    int i = blockIdx.x * blockDim.x + threadIdx.x;
    if (i < n4) out[i] = make_float4(0.f, 0.f, 0.f, 0.f);
}

// --------------------------------------------- coeff = tanh(W @ gw + b), x2
// 2048 warps: one warp per output row (1024 for Wn, 1024 for We)
__global__ void k_coeff(const float* __restrict__ Wn, const float* __restrict__ bn,
                        const float* __restrict__ We, const float* __restrict__ be,
                        const float* __restrict__ gw) {
    int w = (blockIdx.x * blockDim.x + threadIdx.x) >> 5;
    int lane = threadIdx.x & 31;
    const float* W;
    const float* b;
    float* outp;
    int row;
    if (w < DIM) { W = Wn; b = bn; outp = g_cn; row = w; }
    else         { W = We; b = be; outp = g_ce; row = w - DIM; }
    const float4* Wr = (const float4*)(W + row * DIM);
    const float4* g4 = (const float4*)gw;
    float acc = 0.f;
#pragma unroll
    for (int i = 0; i < 8; i++) {
        int k = i * 32 + lane;
        float4 a = Wr[k], g = g4[k];
        acc += a.x * g.x + a.y * g.y + a.z * g.z + a.w * g.w;
    }
#pragma unroll
    for (int o = 16; o; o >>= 1) acc += __shfl_xor_sync(0xffffffffu, acc, o);
    if (lane == 0) outp[row] = tanhf(acc + b[row]);
}

// ----------------------- Mp[m,n] = act( sum_k x1[m,k]*cn[k]*x2[n,k] ), 48x48
// warp-per-output, lanes split K
__global__ void k_mp(const float* __restrict__ x1, const float* __restrict__ x2) {
    int w = (blockIdx.x * blockDim.x + threadIdx.x) >> 5;   // 0..2303
    int lane = threadIdx.x & 31;
    int m = w / N_NODES, n = w % N_NODES;
    const float4* A = (const float4*)(x1 + m * DIM);
    const float4* B = (const float4*)(x2 + n * DIM);
    const float4* C = (const float4*)g_cn;
    float acc = 0.f;
#pragma unroll
    for (int i = 0; i < 8; i++) {
        int k = i * 32 + lane;
        float4 a = A[k], b = B[k], c = C[k];
        acc += (a.x * c.x) * b.x + (a.y * c.y) * b.y +
               (a.z * c.z) * b.z + (a.w * c.w) * b.w;
    }
#pragma unroll
    for (int o = 16; o; o >>= 1) acc += __shfl_xor_sync(0xffffffffu, acc, o);
    if (lane == 0) g_Mp[w] = softplus_act(acc);
}

// ---------------- Me raw GEMM: C[m,n] = sum_k ef1[m,k]*ce[k]*ef2[n,k], 192x192
// 64x64 tile, 4x4 per thread, split-K into SPLITK partials, grid (3,3,SPLITK)
__global__ void k_me(const float* __restrict__ ef1, const float* __restrict__ ef2) {
    __shared__ float As[64][17];
    __shared__ float Bs[64][17];
    int t = threadIdx.x;
    int tx = t & 15, ty = t >> 4;
    int bx = blockIdx.x, by = blockIdx.y, kz = blockIdx.z;
    int lr = t >> 2;          // 0..63  (smem load row)
    int lc = (t & 3) * 4;     // 0,4,8,12 (smem load col base)
    float acc[4][4] = {};
    int k0 = kz * KC;
    const float* Arow = ef1 + (by * 64 + lr) * DIM;
    const float* Brow = ef2 + (bx * 64 + lr) * DIM;

    for (int kb = k0; kb < k0 + KC; kb += 16) {
        float4 c4 = *(const float4*)(g_ce + kb + lc);
        float4 a4 = *(const float4*)(Arow + kb + lc);
        float4 b4 = *(const float4*)(Brow + kb + lc);
        As[lr][lc + 0] = a4.x * c4.x; As[lr][lc + 1] = a4.y * c4.y;
        As[lr][lc + 2] = a4.z * c4.z; As[lr][lc + 3] = a4.w * c4.w;
        Bs[lr][lc + 0] = b4.x; Bs[lr][lc + 1] = b4.y;
        Bs[lr][lc + 2] = b4.z; Bs[lr][lc + 3] = b4.w;
        __syncthreads();
#pragma unroll
        for (int kk = 0; kk < 16; kk++) {
            float a[4], b[4];
#pragma unroll
            for (int j = 0; j < 4; j++) a[j] = As[ty + 16 * j][kk];
#pragma unroll
            for (int i = 0; i < 4; i++) b[i] = Bs[tx + 16 * i][kk];
#pragma unroll
            for (int j = 0; j < 4; j++)
#pragma unroll
                for (int i = 0; i < 4; i++)
                    acc[j][i] += a[j] * b[i];
        }
        __syncthreads();
    }

    float* outp = g_MePart[kz];
#pragma unroll
    for (int j = 0; j < 4; j++) {
        int m = by * 64 + ty + 16 * j;
#pragma unroll
        for (int i = 0; i < 4; i++) {
            int n = bx * 64 + tx + 16 * i;
            outp[m * N_EDGES + n] = acc[j][i];
        }
    }
}

// ------------- reduce partials, activate, scatter-add into M; plus diagonal.
// value for pair (j1,j2) is Me[j2,j1]:
//   M[src2[j2]*48+src1[j1], dst2[j2]*48+dst1[j1]] += act(Me[j2,j1])
__global__ void k_scatter(const int* __restrict__ ei1, const int* __restrict__ ei2,
                          float* __restrict__ M) {
    int idx = blockIdx.x * blockDim.x + threadIdx.x;
    if (idx < EE) {
        float s = 0.f;
#pragma unroll
        for (int z = 0; z < SPLITK; z++) s += g_MePart[z][idx];
        float v = softplus_act(s);
        if (v > 0.f) {
            int j2 = idx / N_EDGES;   // row of Me  (ef1 index)
            int j1 = idx % N_EDGES;   // col of Me  (ef2 index)
            int r = ei2[j2] * N_NODES + ei1[j1];                      // heads (G)
            int c = ei2[N_EDGES + j2] * N_NODES + ei1[N_EDGES + j1];  // tails (H)
            atomicAdd(M + r * OUT_DIM + c, v);
        }
    } else if (idx < EE + NN) {
        int a = idx - EE;
        atomicAdd(M + a * (OUT_DIM + 1), g_Mp[a]);
    }
}

extern "C" void kernel_launch(void* const* d_in, const int* in_sizes, int n_in,
                              void* d_out, int out_size) {
    const float* x1  = (const float*)d_in[0];
    const float* x2  = (const float*)d_in[1];
    const float* ef1 = (const float*)d_in[2];
    const float* ef2 = (const float*)d_in[3];
    const float* gw  = (const float*)d_in[4];
    const float* Wn  = (const float*)d_in[5];
    const float* bn  = (const float*)d_in[6];
    const float* We  = (const float*)d_in[7];
    const float* be  = (const float*)d_in[8];
    const int*   ei1 = (const int*)d_in[9];
    const int*   ei2 = (const int*)d_in[10];
    float* M = (float*)d_out;

    int n4 = (OUT_DIM * OUT_DIM) / 4;              // 1,327,104 float4
    k_zero<<<(n4 + 255) / 256, 256>>>((float4*)M, n4);
    k_coeff<<<256, 256>>>(Wn, bn, We, be, gw);     // 2048 warps
    k_mp<<<288, 256>>>(x1, x2);                    // 2304 warps
    dim3 gme(3, 3, SPLITK);
    k_me<<<gme, 256>>>(ef1, ef2);                  // 144 blocks
    k_scatter<<<(EE + NN + 255) / 256, 256>>>(ei1, ei2, M);
}

// round 4
// speedup vs baseline: 1.2220x; 1.2220x over previous
#include <cuda_runtime.h>

#define N_NODES 48
#define N_EDGES 192
#define DIM     1024
#define NN      (N_NODES * N_NODES)   // 2304
#define EE      (N_EDGES * N_EDGES)   // 36864
#define OUT_DIM NN                    // 2304
#define SPLITK  16
#define KC      (DIM / SPLITK)        // 64
#define N4      ((OUT_DIM * OUT_DIM) / 4)   // 1,327,104 float4
#define H4      (N4 / 2)                    // 663,552
#define GEMM_BLOCKS 144                     // 3 x 3 x 16
#define MP_BLOCKS   96
#define MAIN_BLOCKS (GEMM_BLOCKS + MP_BLOCKS)  // 240

// Scratch (no cudaMalloc allowed)
__device__ float g_cn[DIM];
__device__ float g_ce[DIM];
__device__ float g_Mp[NN];
__device__ float g_MePart[SPLITK][EE];

__device__ __forceinline__ float softplus_act(float x) {
    // relu(softplus(x) - 0.5)
    float sp = (x > 20.f) ? x : log1pf(expf(x));
    float v = sp - 0.5f;
    return v > 0.f ? v : 0.f;
}

// ---------------------------------------------------------------------------
// Kernel 1: coeff = tanh(W @ gw + b) for both node/edge weights, PLUS zero
// the first half of the output matrix (write overlaps weight reads).
// 256 blocks x 256 threads = 2048 warps (one per output row).
// ---------------------------------------------------------------------------
__global__ void k_coeff(const float* __restrict__ Wn, const float* __restrict__ bn,
                        const float* __restrict__ We, const float* __restrict__ be,
                        const float* __restrict__ gw, float4* __restrict__ out4) {
    // fire-and-forget zero stores for M[0 : H4)
    {
        float4 z = make_float4(0.f, 0.f, 0.f, 0.f);
        for (int i = blockIdx.x * 256 + threadIdx.x; i < H4; i += 256 * 256)
            out4[i] = z;
    }
    int w = (blockIdx.x * blockDim.x + threadIdx.x) >> 5;
    int lane = threadIdx.x & 31;
    const float* W;
    const float* b;
    float* outp;
    int row;
    if (w < DIM) { W = Wn; b = bn; outp = g_cn; row = w; }
    else         { W = We; b = be; outp = g_ce; row = w - DIM; }
    const float4* Wr = (const float4*)(W + row * DIM);
    const float4* g4 = (const float4*)gw;
    float acc = 0.f;
#pragma unroll
    for (int i = 0; i < 8; i++) {
        int k = i * 32 + lane;
        float4 a = Wr[k], g = g4[k];
        acc += a.x * g.x + a.y * g.y + a.z * g.z + a.w * g.w;
    }
#pragma unroll
    for (int o = 16; o; o >>= 1) acc += __shfl_xor_sync(0xffffffffu, acc, o);
    if (lane == 0) outp[row] = tanhf(acc + b[row]);
}

// ---------------------------------------------------------------------------
// Kernel 2 (fused): blocks 0..143 -> Me split-K GEMM partials,
//                   blocks 144..239 -> Mp (48x48), all blocks zero M[H4:N4).
// GEMM: 64x64 tile, k-major smem, thread computes contiguous 4x4 C tile so
// the inner loop is 2x LDS.128 + 16 FFMA per kk per thread.
// ---------------------------------------------------------------------------
__global__ void __launch_bounds__(256, 2)
k_main(const float* __restrict__ ef1, const float* __restrict__ ef2,
       const float* __restrict__ x1, const float* __restrict__ x2,
       float4* __restrict__ out4) {
    // fire-and-forget zero stores for M[H4 : N4)
    {
        float4 z = make_float4(0.f, 0.f, 0.f, 0.f);
        for (int i = H4 + blockIdx.x * 256 + threadIdx.x; i < N4; i += MAIN_BLOCKS * 256)
            out4[i] = z;
    }
    int t = threadIdx.x;

    if (blockIdx.x < GEMM_BLOCKS) {
        // ---- Me GEMM partial: C[m,n] = sum_k ef1[m,k]*ce[k]*ef2[n,k]
        __shared__ float4 As[16][17];   // [kk][rowgroup], row r -> As[kk][r>>2].(r&3)
        __shared__ float4 Bs[16][17];
        float* Asf = (float*)As;        // row stride 68 floats
        float* Bsf = (float*)Bs;

        int tx = t & 15, ty = t >> 4;
        int bx = blockIdx.x % 3;
        int by = (blockIdx.x / 3) % 3;
        int kz = blockIdx.x / 9;        // 0..15
        int lr = t >> 2;                // 0..63 (tile row this thread loads)
        int lc = (t & 3) * 4;           // 0,4,8,12 (k-chunk base)
        float acc[4][4] = {};
        int k0 = kz * KC;
        const float* Arow = ef1 + (by * 64 + lr) * DIM;
        const float* Brow = ef2 + (bx * 64 + lr) * DIM;

        for (int kb = k0; kb < k0 + KC; kb += 16) {
            float4 c4 = *(const float4*)(g_ce + kb + lc);
            float4 a4 = *(const float4*)(Arow + kb + lc);
            float4 b4 = *(const float4*)(Brow + kb + lc);
            a4.x *= c4.x; a4.y *= c4.y; a4.z *= c4.z; a4.w *= c4.w;
            Asf[(lc + 0) * 68 + lr] = a4.x;
            Asf[(lc + 1) * 68 + lr] = a4.y;
            Asf[(lc + 2) * 68 + lr] = a4.z;
            Asf[(lc + 3) * 68 + lr] = a4.w;
            Bsf[(lc + 0) * 68 + lr] = b4.x;
            Bsf[(lc + 1) * 68 + lr] = b4.y;
            Bsf[(lc + 2) * 68 + lr] = b4.z;
            Bsf[(lc + 3) * 68 + lr] = b4.w;
            __syncthreads();
#pragma unroll
            for (int kk = 0; kk < 16; kk++) {
                float4 av = As[kk][ty];
                float4 bv = Bs[kk][tx];
                float a[4] = {av.x, av.y, av.z, av.w};
                float b[4] = {bv.x, bv.y, bv.z, bv.w};
#pragma unroll
                for (int j = 0; j < 4; j++)
#pragma unroll
                    for (int i = 0; i < 4; i++)
                        acc[j][i] += a[j] * b[i];
            }
            __syncthreads();
        }

        float* outp = g_MePart[kz];
#pragma unroll
        for (int j = 0; j < 4; j++) {
            int m = by * 64 + 4 * ty + j;
            int n = bx * 64 + 4 * tx;
            *(float4*)(outp + m * N_EDGES + n) =
                make_float4(acc[j][0], acc[j][1], acc[j][2], acc[j][3]);
        }
    } else {
        // ---- Mp: 768 warps, 3 outputs per warp (same m, A row reused)
        int w = (blockIdx.x - GEMM_BLOCKS) * 8 + (t >> 5);  // 0..767
        int lane = t & 31;
        int idx0 = w * 3;
        int m = idx0 / N_NODES, n0 = idx0 % N_NODES;  // 48 % 3 == 0 -> same m
        const float4* A  = (const float4*)(x1 + m * DIM);
        const float4* B0 = (const float4*)(x2 + n0 * DIM);
        const float4* C  = (const float4*)g_cn;
        float s0 = 0.f, s1 = 0.f, s2 = 0.f;
#pragma unroll
        for (int i = 0; i < 8; i++) {
            int k = i * 32 + lane;
            float4 a = A[k], c = C[k];
            a.x *= c.x; a.y *= c.y; a.z *= c.z; a.w *= c.w;
            float4 b0 = B0[k], b1 = B0[256 + k], b2 = B0[512 + k];
            s0 += a.x * b0.x + a.y * b0.y + a.z * b0.z + a.w * b0.w;
            s1 += a.x * b1.x + a.y * b1.y + a.z * b1.z + a.w * b1.w;
            s2 += a.x * b2.x + a.y * b2.y + a.z * b2.z + a.w * b2.w;
        }
#pragma unroll
        for (int o = 16; o; o >>= 1) {
            s0 += __shfl_xor_sync(0xffffffffu, s0, o);
            s1 += __shfl_xor_sync(0xffffffffu, s1, o);
            s2 += __shfl_xor_sync(0xffffffffu, s2, o);
        }
        if (lane == 0) {
            g_Mp[idx0 + 0] = softplus_act(s0);
            g_Mp[idx0 + 1] = softplus_act(s1);
            g_Mp[idx0 + 2] = softplus_act(s2);
        }
    }
}

// ---------------------------------------------------------------------------
// Kernel 3: reduce split-K partials, activate, scatter-add into M + diagonal.
// value for pair (j1,j2) is Me.flat[j2*192+j1]:
//   M[head2[j2]*48+head1[j1], tail2[j2]*48+tail1[j1]] += act(.)
// ---------------------------------------------------------------------------
__global__ void k_scatter(const int* __restrict__ ei1, const int* __restrict__ ei2,
                          float* __restrict__ M) {
    int idx = blockIdx.x * blockDim.x + threadIdx.x;
    if (idx < EE) {
        float s = 0.f;
#pragma unroll
        for (int z = 0; z < SPLITK; z++) s += g_MePart[z][idx];
        float v = softplus_act(s);
        if (v > 0.f) {
            int j2 = idx / N_EDGES;   // row of Me flat view
            int j1 = idx % N_EDGES;   // col of Me flat view
            int r = ei2[j2] * N_NODES + ei1[j1];                      // heads (G)
            int c = ei2[N_EDGES + j2] * N_NODES + ei1[N_EDGES + j1];  // tails (H)
            atomicAdd(M + r * OUT_DIM + c, v);
        }
    } else if (idx < EE + NN) {
        int a = idx - EE;
        atomicAdd(M + a * (OUT_DIM + 1), g_Mp[a]);
    }
}

extern "C" void kernel_launch(void* const* d_in, const int* in_sizes, int n_in,
                              void* d_out, int out_size) {
    const float* x1  = (const float*)d_in[0];
    const float* x2  = (const float*)d_in[1];
    const float* ef1 = (const float*)d_in[2];
    const float* ef2 = (const float*)d_in[3];
    const float* gw  = (const float*)d_in[4];
    const float* Wn  = (const float*)d_in[5];
    const float* bn  = (const float*)d_in[6];
    const float* We  = (const float*)d_in[7];
    const float* be  = (const float*)d_in[8];
    const int*   ei1 = (const int*)d_in[9];
    const int*   ei2 = (const int*)d_in[10];
    float* M = (float*)d_out;

    k_coeff<<<256, 256>>>(Wn, bn, We, be, gw, (float4*)M);
    k_main<<<MAIN_BLOCKS, 256>>>(ef1, ef2, x1, x2, (float4*)M);
    k_scatter<<<(EE + NN + 255) / 256, 256>>>(ei1, ei2, M);
}

// round 5
// speedup vs baseline: 1.2429x; 1.0171x over previous
#include <cuda_runtime.h>

#define N_NODES 48
#define N_EDGES 192
#define DIM     1024
#define NN      (N_NODES * N_NODES)   // 2304
#define EE      (N_EDGES * N_EDGES)   // 36864
#define OUT_DIM NN                    // 2304
#define SPLITK  16
#define KC      (DIM / SPLITK)        // 64
#define N4      ((OUT_DIM * OUT_DIM) / 4)   // 1,327,104 float4
#define Z1      ((N4 / 4) * 3)              // 995,328 float4 zeroed by k_coeff
#define GEMM_BLOCKS 144                     // 3 x 3 x 16
#define MP_BLOCKS   96
#define MAIN_BLOCKS (GEMM_BLOCKS + MP_BLOCKS)  // 240
#define COEFF_BLOCKS (2 * DIM)              // 2048, one per output row
#define COEFF_THREADS 128

// Scratch (no cudaMalloc allowed)
__device__ float g_cn[DIM];
__device__ float g_ce[DIM];
__device__ float g_Mp[NN];
__device__ float g_MePart[SPLITK][EE];

__device__ __forceinline__ float softplus_act(float x) {
    // relu(softplus(x) - 0.5)
    float sp = (x > 20.f) ? x : log1pf(expf(x));
    float v = sp - 0.5f;
    return v > 0.f ? v : 0.f;
}

// ---------------------------------------------------------------------------
// Kernel 1: coeff = tanh(W @ gw + b), block-per-row (2048 blocks x 128 thr).
// Each thread loads 2 float4 of the row -> warp reduce -> smem reduce.
// Also zeroes the first 3/4 of the output matrix (writes overlap reads).
// ---------------------------------------------------------------------------
__global__ void __launch_bounds__(COEFF_THREADS)
k_coeff(const float* __restrict__ Wn, const float* __restrict__ bn,
        const float* __restrict__ We, const float* __restrict__ be,
        const float* __restrict__ gw, float4* __restrict__ out4) {
    int t = threadIdx.x;
    int row = blockIdx.x;            // 0..2047

    // fire-and-forget zero stores for M[0 : Z1)
    {
        float4 z = make_float4(0.f, 0.f, 0.f, 0.f);
        for (int i = row * COEFF_THREADS + t; i < Z1; i += COEFF_BLOCKS * COEFF_THREADS)
            out4[i] = z;
    }

    const float* W;
    const float* b;
    float* outp;
    int r;
    if (row < DIM) { W = Wn; b = bn; outp = g_cn; r = row; }
    else           { W = We; b = be; outp = g_ce; r = row - DIM; }

    const float4* Wr = (const float4*)(W + r * DIM);
    const float4* g4 = (const float4*)gw;
    float acc = 0.f;
#pragma unroll
    for (int i = 0; i < 2; i++) {
        int k = t + COEFF_THREADS * i;           // 0..255 float4
        float4 a = Wr[k], g = g4[k];
        acc += a.x * g.x + a.y * g.y + a.z * g.z + a.w * g.w;
    }
#pragma unroll
    for (int o = 16; o; o >>= 1) acc += __shfl_xor_sync(0xffffffffu, acc, o);

    __shared__ float sred[COEFF_THREADS / 32];
    if ((t & 31) == 0) sred[t >> 5] = acc;
    __syncthreads();
    if (t == 0) {
        float s = sred[0] + sred[1] + sred[2] + sred[3];
        outp[r] = tanhf(s + b[r]);
    }
}

// ---------------------------------------------------------------------------
// Kernel 2 (fused): blocks 0..143 -> Me split-K GEMM partials,
//                   blocks 144..239 -> Mp (48x48), all blocks zero M[Z1:N4).
// GEMM: 64x64 tile, k-major smem, thread computes contiguous 4x4 C tile so
// the inner loop is 2x LDS.128 + 16 FFMA per kk per thread.
// ---------------------------------------------------------------------------
__global__ void __launch_bounds__(256, 2)
k_main(const float* __restrict__ ef1, const float* __restrict__ ef2,
       const float* __restrict__ x1, const float* __restrict__ x2,
       float4* __restrict__ out4) {
    // fire-and-forget zero stores for M[Z1 : N4)
    {
        float4 z = make_float4(0.f, 0.f, 0.f, 0.f);
        for (int i = Z1 + blockIdx.x * 256 + threadIdx.x; i < N4; i += MAIN_BLOCKS * 256)
            out4[i] = z;
    }
    int t = threadIdx.x;

    if (blockIdx.x < GEMM_BLOCKS) {
        // ---- Me GEMM partial: C[m,n] = sum_k ef1[m,k]*ce[k]*ef2[n,k]
        __shared__ float4 As[16][17];   // [kk][rowgroup], row r -> As[kk][r>>2].(r&3)
        __shared__ float4 Bs[16][17];
        float* Asf = (float*)As;        // row stride 68 floats
        float* Bsf = (float*)Bs;

        int tx = t & 15, ty = t >> 4;
        int bx = blockIdx.x % 3;
        int by = (blockIdx.x / 3) % 3;
        int kz = blockIdx.x / 9;        // 0..15
        int lr = t >> 2;                // 0..63 (tile row this thread loads)
        int lc = (t & 3) * 4;           // 0,4,8,12 (k-chunk base)
        float acc[4][4] = {};
        int k0 = kz * KC;
        const float* Arow = ef1 + (by * 64 + lr) * DIM;
        const float* Brow = ef2 + (bx * 64 + lr) * DIM;

        for (int kb = k0; kb < k0 + KC; kb += 16) {
            float4 c4 = *(const float4*)(g_ce + kb + lc);
            float4 a4 = *(const float4*)(Arow + kb + lc);
            float4 b4 = *(const float4*)(Brow + kb + lc);
            a4.x *= c4.x; a4.y *= c4.y; a4.z *= c4.z; a4.w *= c4.w;
            Asf[(lc + 0) * 68 + lr] = a4.x;
            Asf[(lc + 1) * 68 + lr] = a4.y;
            Asf[(lc + 2) * 68 + lr] = a4.z;
            Asf[(lc + 3) * 68 + lr] = a4.w;
            Bsf[(lc + 0) * 68 + lr] = b4.x;
            Bsf[(lc + 1) * 68 + lr] = b4.y;
            Bsf[(lc + 2) * 68 + lr] = b4.z;
            Bsf[(lc + 3) * 68 + lr] = b4.w;
            __syncthreads();
#pragma unroll
            for (int kk = 0; kk < 16; kk++) {
                float4 av = As[kk][ty];
                float4 bv = Bs[kk][tx];
                float a[4] = {av.x, av.y, av.z, av.w};
                float b[4] = {bv.x, bv.y, bv.z, bv.w};
#pragma unroll
                for (int j = 0; j < 4; j++)
#pragma unroll
                    for (int i = 0; i < 4; i++)
                        acc[j][i] += a[j] * b[i];
            }
            __syncthreads();
        }

        float* outp = g_MePart[kz];
#pragma unroll
        for (int j = 0; j < 4; j++) {
            int m = by * 64 + 4 * ty + j;
            int n = bx * 64 + 4 * tx;
            *(float4*)(outp + m * N_EDGES + n) =
                make_float4(acc[j][0], acc[j][1], acc[j][2], acc[j][3]);
        }
    } else {
        // ---- Mp: 768 warps, 3 outputs per warp (same m, A row reused)
        int w = (blockIdx.x - GEMM_BLOCKS) * 8 + (t >> 5);  // 0..767
        int lane = t & 31;
        int idx0 = w * 3;
        int m = idx0 / N_NODES, n0 = idx0 % N_NODES;  // 48 % 3 == 0 -> same m
        const float4* A  = (const float4*)(x1 + m * DIM);
        const float4* B0 = (const float4*)(x2 + n0 * DIM);
        const float4* C  = (const float4*)g_cn;
        float s0 = 0.f, s1 = 0.f, s2 = 0.f;
#pragma unroll
        for (int i = 0; i < 8; i++) {
            int k = i * 32 + lane;
            float4 a = A[k], c = C[k];
            a.x *= c.x; a.y *= c.y; a.z *= c.z; a.w *= c.w;
            float4 b0 = B0[k], b1 = B0[256 + k], b2 = B0[512 + k];
            s0 += a.x * b0.x + a.y * b0.y + a.z * b0.z + a.w * b0.w;
            s1 += a.x * b1.x + a.y * b1.y + a.z * b1.z + a.w * b1.w;
            s2 += a.x * b2.x + a.y * b2.y + a.z * b2.z + a.w * b2.w;
        }
#pragma unroll
        for (int o = 16; o; o >>= 1) {
            s0 += __shfl_xor_sync(0xffffffffu, s0, o);
            s1 += __shfl_xor_sync(0xffffffffu, s1, o);
            s2 += __shfl_xor_sync(0xffffffffu, s2, o);
        }
        if (lane == 0) {
            g_Mp[idx0 + 0] = softplus_act(s0);
            g_Mp[idx0 + 1] = softplus_act(s1);
            g_Mp[idx0 + 2] = softplus_act(s2);
        }
    }
}

// ---------------------------------------------------------------------------
// Kernel 3: reduce split-K partials, activate, scatter-add into M + diagonal.
// value for pair (j1,j2) is Me.flat[j2*192+j1]:
//   M[head2[j2]*48+head1[j1], tail2[j2]*48+tail1[j1]] += act(.)
// ---------------------------------------------------------------------------
__global__ void k_scatter(const int* __restrict__ ei1, const int* __restrict__ ei2,
                          float* __restrict__ M) {
    int idx = blockIdx.x * blockDim.x + threadIdx.x;
    if (idx < EE) {
        float s = 0.f;
#pragma unroll
        for (int z = 0; z < SPLITK; z++) s += g_MePart[z][idx];
        float v = softplus_act(s);
        if (v > 0.f) {
            int j2 = idx / N_EDGES;   // row of Me flat view
            int j1 = idx % N_EDGES;   // col of Me flat view
            int r = ei2[j2] * N_NODES + ei1[j1];                      // heads (G)
            int c = ei2[N_EDGES + j2] * N_NODES + ei1[N_EDGES + j1];  // tails (H)
            atomicAdd(M + r * OUT_DIM + c, v);
        }
    } else if (idx < EE + NN) {
        int a = idx - EE;
        atomicAdd(M + a * (OUT_DIM + 1), g_Mp[a]);
    }
}

extern "C" void kernel_launch(void* const* d_in, const int* in_sizes, int n_in,
                              void* d_out, int out_size) {
    const float* x1  = (const float*)d_in[0];
    const float* x2  = (const float*)d_in[1];
    const float* ef1 = (const float*)d_in[2];
    const float* ef2 = (const float*)d_in[3];
    const float* gw  = (const float*)d_in[4];
    const float* Wn  = (const float*)d_in[5];
    const float* bn  = (const float*)d_in[6];
    const float* We  = (const float*)d_in[7];
    const float* be  = (const float*)d_in[8];
    const int*   ei1 = (const int*)d_in[9];
    const int*   ei2 = (const int*)d_in[10];
    float* M = (float*)d_out;

    k_coeff<<<COEFF_BLOCKS, COEFF_THREADS>>>(Wn, bn, We, be, gw, (float4*)M);
    k_main<<<MAIN_BLOCKS, 256>>>(ef1, ef2, x1, x2, (float4*)M);
    k_scatter<<<(EE + NN + 255) / 256, 256>>>(ei1, ei2, M);
}